// round 12
// baseline (speedup 1.0000x reference)
#include <cuda_runtime.h>
#include <cuda_fp16.h>
#include <mma.h>
#include <cstdint>

using namespace nvcuda;

#define BN     50000
#define NBR    4
#define DD     32
#define CC     128          // NBR*DD
#define MM     256
#define NODES  (BN + MM)    // 50256
#define CAPR   128          // per-batch-row bucket capacity (mean ~40)
#define HROWS  64           // rows per compute_h block
#define XPAD   132          // padded row stride (floats)
#define YROWS  64           // rows per y block

// scratch (static device globals — no allocation)
__device__ __half g_h16[(size_t)NODES * CC];   // 12.9MB (Y path only)
__device__ __half g_out16[(size_t)BN * CC];    // gather result, fp16 (y input)
__device__ __half g_wfc16[CC * CC];            // W_fc in fp16
__device__ int    g_cnt[BN];
__device__ int2   g_ent[(size_t)BN * CAPR];    // (src_row, w_bits) per batch-dst
__device__ float  g_vq32[MM * CC];             // vq_grad re-laid [m][b*32+e], 128KB
__device__ float  g_info;

// ---------------------------------------------------------------------------
// prep: zero counters/info + relayout vq_grad + convert W_fc to fp16
// ---------------------------------------------------------------------------
__global__ void prep_kernel(const float* __restrict__ vq_grad,
                            const float* __restrict__ W_fc) {
    const int idx = blockIdx.x * blockDim.x + threadIdx.x;
    if (idx < NBR * MM * DD) {
        const int b = idx >> 13;
        const int m = (idx >> 5) & (MM - 1);
        const int e = idx & 31;
        g_vq32[m * CC + b * DD + e] = vq_grad[idx];
    }
    if (idx < CC * CC) g_wfc16[idx] = __float2half_rn(W_fc[idx]);
    if (idx < BN) g_cnt[idx] = 0;
    if (idx == 0) g_info = 0.0f;
}

// ---------------------------------------------------------------------------
// Bucket all edges by destination batch row (1 edge per thread).
// ---------------------------------------------------------------------------
__global__ void fill_dst_kernel(const int* __restrict__ sbb, const int* __restrict__ dbb,
                                const float* __restrict__ wbb,
                                const int* __restrict__ sbm, const int* __restrict__ dbm,
                                const float* __restrict__ wbm,
                                const int* __restrict__ cidx, int Ebb, int Etot) {
    const int i = blockIdx.x * blockDim.x + threadIdx.x;
    if (i >= Etot) return;
    int r, s; float w;
    if (i < Ebb) { r = dbb[i]; s = sbb[i]; w = wbb[i]; }
    else { const int j = i - Ebb; r = dbm[j]; s = BN + cidx[sbm[j]]; w = wbm[j]; }
    const int pos = atomicAdd(&g_cnt[r], 1);
    if (pos < CAPR)
        g_ent[(size_t)r * CAPR + pos] = make_int2(s, __float_as_int(w));
}

// ---------------------------------------------------------------------------
// compute_h: register-tiled GEMM, PURE (no info/vsum dependency).
// ---------------------------------------------------------------------------
__global__ void compute_h_kernel(const float* __restrict__ X,
                                 const float* __restrict__ codebook,
                                 const float* __restrict__ W_conv,
                                 const float* __restrict__ wr_p) {
    __shared__ float Ws[NBR * DD * DD];   // 16KB, [b][d][e]
    __shared__ float Xs[HROWS][XPAD];     // 33KB padded

    for (int i = threadIdx.x; i < NBR * DD * DD; i += blockDim.x)
        Ws[i] = W_conv[i];

    const int row0 = blockIdx.x * HROWS;
    const float wr = wr_p[0];

    for (int i = threadIdx.x; i < HROWS * 32; i += 256) {
        const int r  = i >> 5;
        const int c4 = i & 31;
        const int row = row0 + r;
        float4 v = make_float4(0.f, 0.f, 0.f, 0.f);
        if (row < BN) {
            v = ((const float4*)X)[(size_t)row * 32 + c4];
        } else if (row < NODES) {
            const int b = c4 >> 3, sub = c4 & 7, m = row - BN;
            v = ((const float4*)codebook)[((size_t)b * MM + m) * 8 + sub];
            v.x *= wr; v.y *= wr; v.z *= wr; v.w *= wr;
        }
        *(float4*)&Xs[r][c4 * 4] = v;
    }
    __syncthreads();

    const int wid  = threadIdx.x >> 5;
    const int lane = threadIdx.x & 31;
    const int rgrp = wid >> 2;
    const int b    = wid & 3;
    const int rg   = lane >> 2;
    const int cg   = lane & 3;

    float acc[4][8];
    #pragma unroll
    for (int rr = 0; rr < 4; rr++)
        #pragma unroll
        for (int c = 0; c < 8; c++) acc[rr][c] = 0.0f;

    const float* wbp = &Ws[b * (DD * DD) + cg * 8];
    const int lrow0 = rgrp * 32 + rg;

    #pragma unroll
    for (int d = 0; d < DD; d++) {
        const float4 wv0 = *(const float4*)(wbp + d * DD);
        const float4 wv1 = *(const float4*)(wbp + d * DD + 4);
        #pragma unroll
        for (int rr = 0; rr < 4; rr++) {
            const float xv = Xs[lrow0 + 8 * rr][b * DD + d];
            acc[rr][0] = fmaf(xv, wv0.x, acc[rr][0]);
            acc[rr][1] = fmaf(xv, wv0.y, acc[rr][1]);
            acc[rr][2] = fmaf(xv, wv0.z, acc[rr][2]);
            acc[rr][3] = fmaf(xv, wv0.w, acc[rr][3]);
            acc[rr][4] = fmaf(xv, wv1.x, acc[rr][4]);
            acc[rr][5] = fmaf(xv, wv1.y, acc[rr][5]);
            acc[rr][6] = fmaf(xv, wv1.z, acc[rr][6]);
            acc[rr][7] = fmaf(xv, wv1.w, acc[rr][7]);
        }
    }

    #pragma unroll
    for (int rr = 0; rr < 4; rr++) {
        const int row = row0 + lrow0 + 8 * rr;
        if (row < NODES) {
            __half2 h0 = __floats2half2_rn(acc[rr][0], acc[rr][1]);
            __half2 h1 = __floats2half2_rn(acc[rr][2], acc[rr][3]);
            __half2 h2 = __floats2half2_rn(acc[rr][4], acc[rr][5]);
            __half2 h3 = __floats2half2_rn(acc[rr][6], acc[rr][7]);
            uint4 pk;
            pk.x = *(unsigned*)&h0; pk.y = *(unsigned*)&h1;
            pk.z = *(unsigned*)&h2; pk.w = *(unsigned*)&h3;
            *(uint4*)(g_h16 + (size_t)row * CC + b * DD + cg * 8) = pk;
        }
    }
}

// ---------------------------------------------------------------------------
// Gather: one warp per batch row. out16[r] = fp16(b_conv + sum w * h16[src]).
// (byte-identical logic to round 11 — this launch is 4th -> gets profiled)
// ---------------------------------------------------------------------------
__device__ __forceinline__ uint2 load_h(int2 E, int lane) {
    const uint2* hp = (const uint2*)(g_h16 + (size_t)E.x * CC) + lane;
    if (E.x >= BN) return *hp;          // L1-cached (codeword rows hot)
    return __ldcs(hp);                  // streaming
}

__device__ __forceinline__ void fma_h16(float4& acc, int2 ent, uint2 hv) {
    const float w = __int_as_float(ent.y);
    const float2 f0 = __half22float2(*(const __half2*)&hv.x);
    const float2 f1 = __half22float2(*(const __half2*)&hv.y);
    acc.x = fmaf(w, f0.x, acc.x); acc.y = fmaf(w, f0.y, acc.y);
    acc.z = fmaf(w, f1.x, acc.z); acc.w = fmaf(w, f1.y, acc.w);
}

__global__ void gather_kernel(const float* __restrict__ b_conv) {
    const int gw   = (blockIdx.x * blockDim.x + threadIdx.x) >> 5;
    const int lane = threadIdx.x & 31;
    if (gw >= BN) return;
    int n = g_cnt[gw]; if (n > CAPR) n = CAPR;

    float4 acc = ((const float4*)b_conv)[lane];
    const int2* ep = g_ent + (size_t)gw * CAPR;
    const int2 Z = make_int2(0, 0);   // src row 0, w == 0.0f

    int2 E0 = (0 < n) ? __ldcs(ep + 0) : Z;
    int2 E1 = (1 < n) ? __ldcs(ep + 1) : Z;
    int2 E2 = (2 < n) ? __ldcs(ep + 2) : Z;
    int2 E3 = (3 < n) ? __ldcs(ep + 3) : Z;

    for (int e = 0; e < n; e += 4) {
        const int2 N0 = (e + 4 < n) ? __ldcs(ep + e + 4) : Z;
        const int2 N1 = (e + 5 < n) ? __ldcs(ep + e + 5) : Z;
        const int2 N2 = (e + 6 < n) ? __ldcs(ep + e + 6) : Z;
        const int2 N3 = (e + 7 < n) ? __ldcs(ep + e + 7) : Z;
        const uint2 h0 = load_h(E0, lane);
        const uint2 h1 = load_h(E1, lane);
        const uint2 h2 = load_h(E2, lane);
        const uint2 h3 = load_h(E3, lane);
        fma_h16(acc, E0, h0); fma_h16(acc, E1, h1);
        fma_h16(acc, E2, h2); fma_h16(acc, E3, h3);
        E0 = N0; E1 = N1; E2 = N2; E3 = N3;
    }

    __half2 o0 = __floats2half2_rn(acc.x, acc.y);
    __half2 o1 = __floats2half2_rn(acc.z, acc.w);
    uint2 pk;
    pk.x = *(unsigned*)&o0;
    pk.y = *(unsigned*)&o1;
    ((uint2*)(g_out16 + (size_t)gw * CC))[lane] = pk;
}

// ---------------------------------------------------------------------------
// info_kernel: per batch row r, vsum_r = sum_{bm entries} w * vq32[c] kept in
// REGISTERS (no vsum array), then recompute exact fp32 h32[r] (X row + W_conv
// in shared, width-8 shuffle) and accumulate dot(h32[r], vsum_r) -> g_info.
// ---------------------------------------------------------------------------
__device__ __forceinline__ void vs_proc(float4& vs, int2 E, int lane) {
    if (E.x >= BN) {                     // warp-uniform branch
        const float w = __int_as_float(E.y);
        const float4 qv = ((const float4*)(g_vq32 + (size_t)(E.x - BN) * CC))[lane];
        vs.x = fmaf(w, qv.x, vs.x); vs.y = fmaf(w, qv.y, vs.y);
        vs.z = fmaf(w, qv.z, vs.z); vs.w = fmaf(w, qv.w, vs.w);
    }
}

__global__ void info_kernel(const float* __restrict__ X,
                            const float* __restrict__ W_conv) {
    __shared__ float Ws[NBR * DD * DD];   // 16KB, [b][d][e]
    __shared__ float wred[8];
    for (int i = threadIdx.x; i < NBR * DD * DD; i += blockDim.x)
        Ws[i] = W_conv[i];
    __syncthreads();

    const int gw   = (blockIdx.x * blockDim.x + threadIdx.x) >> 5;
    const int lane = threadIdx.x & 31;
    const int wid  = threadIdx.x >> 5;

    float p = 0.0f;
    if (gw < BN) {
        int n = g_cnt[gw]; if (n > CAPR) n = CAPR;
        const int2* ep = g_ent + (size_t)gw * CAPR;
        const int2 Z = make_int2(0, 0);
        float4 vs = make_float4(0.f, 0.f, 0.f, 0.f);

        int2 c0 = (0 < n) ? __ldcs(ep + 0) : Z;
        int2 c1 = (1 < n) ? __ldcs(ep + 1) : Z;
        int2 c2 = (2 < n) ? __ldcs(ep + 2) : Z;
        int2 c3 = (3 < n) ? __ldcs(ep + 3) : Z;
        for (int e = 0; e < n; e += 4) {
            const int2 n0 = (e + 4 < n) ? __ldcs(ep + e + 4) : Z;
            const int2 n1 = (e + 5 < n) ? __ldcs(ep + e + 5) : Z;
            const int2 n2 = (e + 6 < n) ? __ldcs(ep + e + 6) : Z;
            const int2 n3 = (e + 7 < n) ? __ldcs(ep + e + 7) : Z;
            vs_proc(vs, c0, lane); vs_proc(vs, c1, lane);
            vs_proc(vs, c2, lane); vs_proc(vs, c3, lane);
            c0 = n0; c1 = n1; c2 = n2; c3 = n3;
        }

        if (__any_sync(0xFFFFFFFF,
                       vs.x != 0.f || vs.y != 0.f || vs.z != 0.f || vs.w != 0.f)) {
            // recompute exact fp32 h[row, lane*4 .. lane*4+3]
            const int b = lane >> 3;                 // branch of my 4 cols
            const float4 x4 = ((const float4*)(X + (size_t)gw * CC))[lane];
            float h0 = 0.f, h1 = 0.f, h2 = 0.f, h3 = 0.f;
            const float* wb = &Ws[b * (DD * DD) + (lane & 7) * 4];
            #pragma unroll
            for (int i = 0; i < 8; i++) {
                float xs0 = __shfl_sync(0xFFFFFFFF, x4.x, i, 8);
                float xs1 = __shfl_sync(0xFFFFFFFF, x4.y, i, 8);
                float xs2 = __shfl_sync(0xFFFFFFFF, x4.z, i, 8);
                float xs3 = __shfl_sync(0xFFFFFFFF, x4.w, i, 8);
                const float4 w0 = *(const float4*)(wb + (4 * i + 0) * DD);
                const float4 w1 = *(const float4*)(wb + (4 * i + 1) * DD);
                const float4 w2 = *(const float4*)(wb + (4 * i + 2) * DD);
                const float4 w3 = *(const float4*)(wb + (4 * i + 3) * DD);
                h0 = fmaf(xs0, w0.x, h0); h1 = fmaf(xs0, w0.y, h1);
                h2 = fmaf(xs0, w0.z, h2); h3 = fmaf(xs0, w0.w, h3);
                h0 = fmaf(xs1, w1.x, h0); h1 = fmaf(xs1, w1.y, h1);
                h2 = fmaf(xs1, w1.z, h2); h3 = fmaf(xs1, w1.w, h3);
                h0 = fmaf(xs2, w2.x, h0); h1 = fmaf(xs2, w2.y, h1);
                h2 = fmaf(xs2, w2.z, h2); h3 = fmaf(xs2, w2.w, h3);
                h0 = fmaf(xs3, w3.x, h0); h1 = fmaf(xs3, w3.y, h1);
                h2 = fmaf(xs3, w3.z, h2); h3 = fmaf(xs3, w3.w, h3);
            }
            p = h0 * vs.x + h1 * vs.y + h2 * vs.z + h3 * vs.w;
        }
    }

    #pragma unroll
    for (int s = 16; s > 0; s >>= 1)
        p += __shfl_xor_sync(0xFFFFFFFF, p, s);
    if (lane == 0) wred[wid] = p;
    __syncthreads();
    if (threadIdx.x == 0) {
        float s = wred[0] + wred[1] + wred[2] + wred[3]
                + wred[4] + wred[5] + wred[6] + wred[7];
        if (s != 0.0f) atomicAdd(&g_info, s);
    }
}

// ---------------------------------------------------------------------------
// finalize: out_scalar = (g_info + sum b_conv[col]*vq[b,m,e]) * wr
// ---------------------------------------------------------------------------
__global__ void finalize_kernel(const float* __restrict__ vq_grad,
                                const float* __restrict__ b_conv,
                                const float* __restrict__ wr_p,
                                float* __restrict__ out_scalar) {
    __shared__ float red[256];
    float s = 0.0f;
    for (int idx = threadIdx.x; idx < NBR * MM * DD; idx += 256) {
        const int b = idx >> 13;
        const int e = idx & 31;
        s += b_conv[b * DD + e] * vq_grad[idx];
    }
    red[threadIdx.x] = s;
    __syncthreads();
    for (int st = 128; st > 0; st >>= 1) {
        if (threadIdx.x < st) red[threadIdx.x] += red[threadIdx.x + st];
        __syncthreads();
    }
    if (threadIdx.x == 0) *out_scalar = (red[0] + g_info) * wr_p[0];
}

// ---------------------------------------------------------------------------
// y_kernel (WMMA): Y[r,c] = (out16 @ W16)[r,c] + b_fc[c] + X_B[r,c]
// ---------------------------------------------------------------------------
__global__ void y_kernel(const float* __restrict__ X,
                         const float* __restrict__ b_fc,
                         float* __restrict__ Y) {
    __shared__ __align__(16) char sraw[49152];
    __half* As = (__half*)sraw;                   // [64][128]
    __half* Bs = (__half*)(sraw + 16384);         // [128][128]
    float*  Ob = (float*)sraw;                    // [64][128] (after loop)

    const int row0 = blockIdx.x * YROWS;
    const int tid  = threadIdx.x;

    for (int i = tid; i < 1024; i += 256) {
        const int r = i >> 4, c16 = i & 15;
        const int row = row0 + r;
        uint4 v = make_uint4(0, 0, 0, 0);
        if (row < BN) v = ((const uint4*)(g_out16 + (size_t)row * CC))[c16];
        ((uint4*)As)[i] = v;
    }
    for (int i = tid; i < 2048; i += 256)
        ((uint4*)Bs)[i] = ((const uint4*)g_wfc16)[i];
    __syncthreads();

    const int w  = tid >> 5;
    const int rt = w >> 1;          // 0..3
    const int ch = w & 1;           // 0/1

    wmma::fragment<wmma::accumulator, 16, 16, 16, float> accf[4];
    #pragma unroll
    for (int t = 0; t < 4; t++) wmma::fill_fragment(accf[t], 0.0f);

    #pragma unroll
    for (int k = 0; k < 8; k++) {
        wmma::fragment<wmma::matrix_a, 16, 16, 16, __half, wmma::row_major> af;
        wmma::load_matrix_sync(af, As + (rt * 16) * CC + k * 16, CC);
        #pragma unroll
        for (int t = 0; t < 4; t++) {
            wmma::fragment<wmma::matrix_b, 16, 16, 16, __half, wmma::row_major> bf;
            wmma::load_matrix_sync(bf, Bs + (k * 16) * CC + ch * 64 + t * 16, CC);
            wmma::mma_sync(accf[t], af, bf, accf[t]);
        }
    }
    __syncthreads();   // done with As/Bs

    #pragma unroll
    for (int t = 0; t < 4; t++)
        wmma::store_matrix_sync(Ob + (rt * 16) * CC + ch * 64 + t * 16,
                                accf[t], CC, wmma::mem_row_major);
    __syncthreads();

    for (int i = tid; i < YROWS * 32; i += 256) {
        const int r = i >> 5, c4 = i & 31;
        const int row = row0 + r;
        if (row >= BN) continue;
        const float4 ov = ((const float4*)Ob)[r * 32 + c4];
        const float4 bv = ((const float4*)b_fc)[c4];
        const float4 xv = ((const float4*)(X + (size_t)row * CC))[c4];
        ((float4*)(Y + (size_t)row * CC))[c4] =
            make_float4(ov.x + bv.x + xv.x, ov.y + bv.y + xv.y,
                        ov.z + bv.z + xv.z, ov.w + bv.w + xv.w);
    }
}

// ---------------------------------------------------------------------------
extern "C" void kernel_launch(void* const* d_in, const int* in_sizes, int n_in,
                              void* d_out, int out_size) {
    const float* X_B      = (const float*)d_in[0];
    const int*   esrc_bb  = (const int*)  d_in[1];
    const int*   edst_bb  = (const int*)  d_in[2];
    const float* ew_bb    = (const float*)d_in[3];
    const int*   esrc_bm  = (const int*)  d_in[4];
    const int*   edst_bm  = (const int*)  d_in[5];
    const float* ew_bm    = (const float*)d_in[6];
    const int*   c_idx    = (const int*)  d_in[7];
    const float* wr       = (const float*)d_in[8];
    const float* codebook = (const float*)d_in[9];
    const float* vq_grad  = (const float*)d_in[10];
    const float* W_conv   = (const float*)d_in[11];
    const float* b_conv   = (const float*)d_in[12];
    const float* W_fc     = (const float*)d_in[13];
    const float* b_fc     = (const float*)d_in[14];
    float* out = (float*)d_out;

    const int Ebb  = in_sizes[1];
    const int Ebm  = in_sizes[4];
    const int Etot = Ebb + Ebm;

    prep_kernel<<<(BN + 255) / 256, 256>>>(vq_grad, W_fc);                 // 1
    fill_dst_kernel<<<(Etot + 255) / 256, 256>>>(esrc_bb, edst_bb, ew_bb,  // 2
                                                 esrc_bm, edst_bm, ew_bm,
                                                 c_idx, Ebb, Etot);
    compute_h_kernel<<<(NODES + HROWS - 1) / HROWS, 256>>>(X_B, codebook,  // 3
                                                           W_conv, wr);
    gather_kernel<<<(BN * 32 + 255) / 256, 256>>>(b_conv);                 // 4 <- profiled
    info_kernel<<<(BN * 32 + 255) / 256, 256>>>(X_B, W_conv);              // 5
    finalize_kernel<<<1, 256>>>(vq_grad, b_conv, wr, out + (out_size - 1));// 6
    y_kernel<<<(BN + YROWS - 1) / YROWS, 256>>>(X_B, b_fc, out);           // 7
}

// round 13
// speedup vs baseline: 1.2054x; 1.2054x over previous
#include <cuda_runtime.h>
#include <cuda_fp16.h>
#include <mma.h>
#include <cstdint>

using namespace nvcuda;

#define BN     50000
#define NBR    4
#define DD     32
#define CC     128          // NBR*DD
#define MM     256
#define NODES  (BN + MM)    // 50256
#define CAPR   128          // per-batch-row bucket capacity (mean ~40)
#define CSTR   8            // counter stride (ints) -> 32B, no LTS false sharing
#define HROWS  64           // rows per compute_h block
#define XPAD   132          // padded row stride (floats)
#define YROWS  64           // rows per y block

// scratch (static device globals — no allocation)
__device__ __half g_h16[(size_t)NODES * CC];   // 12.9MB (gather path)
__device__ float  g_h32[(size_t)BN * CC];      // 25.6MB exact h, batch rows (info)
__device__ __half g_out16[(size_t)BN * CC];    // gather result, fp16 (y input)
__device__ __half g_wfc16[CC * CC];            // W_fc in fp16
__device__ int    g_cnt[BN * CSTR];            // padded counters (32B apart)
__device__ int2   g_ent[(size_t)BN * CAPR];    // (src_row, w_bits) per batch-dst
__device__ float  g_vq32[MM * CC];             // vq_grad re-laid [m][b*32+e], 128KB
__device__ float  g_vsum[(size_t)BN * CC];     // per-row sum w*vq (fp32)
__device__ float  g_info;

// ---------------------------------------------------------------------------
// prep_a: zero padded counters + info
// ---------------------------------------------------------------------------
__global__ void prep_a_kernel() {
    const int idx = blockIdx.x * blockDim.x + threadIdx.x;
    if (idx < BN) g_cnt[idx * CSTR] = 0;
    if (idx == 0) g_info = 0.0f;
}

// ---------------------------------------------------------------------------
// prep_b: relayout vq_grad [b][m][e] -> [m][b*32+e] + convert W_fc to fp16
// ---------------------------------------------------------------------------
__global__ void prep_b_kernel(const float* __restrict__ vq_grad,
                              const float* __restrict__ W_fc) {
    const int idx = blockIdx.x * blockDim.x + threadIdx.x;
    if (idx < NBR * MM * DD) {
        const int b = idx >> 13;
        const int m = (idx >> 5) & (MM - 1);
        const int e = idx & 31;
        g_vq32[m * CC + b * DD + e] = vq_grad[idx];
    }
    if (idx < CC * CC) g_wfc16[idx] = __float2half_rn(W_fc[idx]);
}

// ---------------------------------------------------------------------------
// compute_h: register-tiled GEMM, pure. Writes h16 (all rows) + h32 (batch).
// ---------------------------------------------------------------------------
__global__ void compute_h_kernel(const float* __restrict__ X,
                                 const float* __restrict__ codebook,
                                 const float* __restrict__ W_conv,
                                 const float* __restrict__ wr_p) {
    __shared__ float Ws[NBR * DD * DD];   // 16KB, [b][d][e]
    __shared__ float Xs[HROWS][XPAD];     // 33KB padded

    for (int i = threadIdx.x; i < NBR * DD * DD; i += blockDim.x)
        Ws[i] = W_conv[i];

    const int row0 = blockIdx.x * HROWS;
    const float wr = wr_p[0];

    for (int i = threadIdx.x; i < HROWS * 32; i += 256) {
        const int r  = i >> 5;
        const int c4 = i & 31;
        const int row = row0 + r;
        float4 v = make_float4(0.f, 0.f, 0.f, 0.f);
        if (row < BN) {
            v = ((const float4*)X)[(size_t)row * 32 + c4];
        } else if (row < NODES) {
            const int b = c4 >> 3, sub = c4 & 7, m = row - BN;
            v = ((const float4*)codebook)[((size_t)b * MM + m) * 8 + sub];
            v.x *= wr; v.y *= wr; v.z *= wr; v.w *= wr;
        }
        *(float4*)&Xs[r][c4 * 4] = v;
    }
    __syncthreads();

    const int wid  = threadIdx.x >> 5;
    const int lane = threadIdx.x & 31;
    const int rgrp = wid >> 2;
    const int b    = wid & 3;
    const int rg   = lane >> 2;
    const int cg   = lane & 3;

    float acc[4][8];
    #pragma unroll
    for (int rr = 0; rr < 4; rr++)
        #pragma unroll
        for (int c = 0; c < 8; c++) acc[rr][c] = 0.0f;

    const float* wbp = &Ws[b * (DD * DD) + cg * 8];
    const int lrow0 = rgrp * 32 + rg;

    #pragma unroll
    for (int d = 0; d < DD; d++) {
        const float4 wv0 = *(const float4*)(wbp + d * DD);
        const float4 wv1 = *(const float4*)(wbp + d * DD + 4);
        #pragma unroll
        for (int rr = 0; rr < 4; rr++) {
            const float xv = Xs[lrow0 + 8 * rr][b * DD + d];
            acc[rr][0] = fmaf(xv, wv0.x, acc[rr][0]);
            acc[rr][1] = fmaf(xv, wv0.y, acc[rr][1]);
            acc[rr][2] = fmaf(xv, wv0.z, acc[rr][2]);
            acc[rr][3] = fmaf(xv, wv0.w, acc[rr][3]);
            acc[rr][4] = fmaf(xv, wv1.x, acc[rr][4]);
            acc[rr][5] = fmaf(xv, wv1.y, acc[rr][5]);
            acc[rr][6] = fmaf(xv, wv1.z, acc[rr][6]);
            acc[rr][7] = fmaf(xv, wv1.w, acc[rr][7]);
        }
    }

    #pragma unroll
    for (int rr = 0; rr < 4; rr++) {
        const int row = row0 + lrow0 + 8 * rr;
        if (row < NODES) {
            __half2 h0 = __floats2half2_rn(acc[rr][0], acc[rr][1]);
            __half2 h1 = __floats2half2_rn(acc[rr][2], acc[rr][3]);
            __half2 h2 = __floats2half2_rn(acc[rr][4], acc[rr][5]);
            __half2 h3 = __floats2half2_rn(acc[rr][6], acc[rr][7]);
            uint4 pk;
            pk.x = *(unsigned*)&h0; pk.y = *(unsigned*)&h1;
            pk.z = *(unsigned*)&h2; pk.w = *(unsigned*)&h3;
            *(uint4*)(g_h16 + (size_t)row * CC + b * DD + cg * 8) = pk;
        }
        if (row < BN) {
            float* hp = g_h32 + (size_t)row * CC + b * DD + cg * 8;
            *(float4*)hp       = make_float4(acc[rr][0], acc[rr][1], acc[rr][2], acc[rr][3]);
            *(float4*)(hp + 4) = make_float4(acc[rr][4], acc[rr][5], acc[rr][6], acc[rr][7]);
        }
    }
}

// ---------------------------------------------------------------------------
// fill (launch position 4 -> gets profiled): bucket edges by dst batch row.
// Counters padded to 32B stride (g_cnt[r*CSTR]) to avoid LTS sector
// false-sharing on the 2M ticket atomics.
// ---------------------------------------------------------------------------
__global__ void fill_dst_kernel(const int* __restrict__ sbb, const int* __restrict__ dbb,
                                const float* __restrict__ wbb,
                                const int* __restrict__ sbm, const int* __restrict__ dbm,
                                const float* __restrict__ wbm,
                                const int* __restrict__ cidx, int Ebb, int Etot) {
    const int i = blockIdx.x * blockDim.x + threadIdx.x;
    if (i >= Etot) return;
    int r, s; float w;
    if (i < Ebb) { r = dbb[i]; s = sbb[i]; w = wbb[i]; }
    else { const int j = i - Ebb; r = dbm[j]; s = BN + cidx[sbm[j]]; w = wbm[j]; }
    const int pos = atomicAdd(&g_cnt[r * CSTR], 1);
    if (pos < CAPR)
        g_ent[(size_t)r * CAPR + pos] = make_int2(s, __float_as_int(w));
}

// ---------------------------------------------------------------------------
// gather (fused): single bucket walk per row produces BOTH
//   out16[r] = fp16(b_conv + sum w * h16[src])
//   vsum[r]  = sum_{src>=BN} w * vq32[src-BN]   (fp32, info path)
// ---------------------------------------------------------------------------
__device__ __forceinline__ void gfma(float4& acc, float4& vs, int2 E, uint2 hv,
                                     int lane) {
    const float w = __int_as_float(E.y);
    const float2 f0 = __half22float2(*(const __half2*)&hv.x);
    const float2 f1 = __half22float2(*(const __half2*)&hv.y);
    acc.x = fmaf(w, f0.x, acc.x); acc.y = fmaf(w, f0.y, acc.y);
    acc.z = fmaf(w, f1.x, acc.z); acc.w = fmaf(w, f1.y, acc.w);
    if (E.x >= BN) {   // warp-uniform
        const float4 qv = ((const float4*)(g_vq32 + (size_t)(E.x - BN) * CC))[lane];
        vs.x = fmaf(w, qv.x, vs.x); vs.y = fmaf(w, qv.y, vs.y);
        vs.z = fmaf(w, qv.z, vs.z); vs.w = fmaf(w, qv.w, vs.w);
    }
}

__global__ void gather_kernel(const float* __restrict__ b_conv) {
    const int gw   = (blockIdx.x * blockDim.x + threadIdx.x) >> 5;
    const int lane = threadIdx.x & 31;
    if (gw >= BN) return;
    int n = g_cnt[gw * CSTR]; if (n > CAPR) n = CAPR;

    float4 acc = ((const float4*)b_conv)[lane];
    float4 vs  = make_float4(0.f, 0.f, 0.f, 0.f);
    const int2* ep = g_ent + (size_t)gw * CAPR;
    const int2 Z = make_int2(0, 0);   // src 0 (<BN), w == 0.0f

    int2 E0 = (0 < n) ? __ldcs(ep + 0) : Z;
    int2 E1 = (1 < n) ? __ldcs(ep + 1) : Z;
    int2 E2 = (2 < n) ? __ldcs(ep + 2) : Z;
    int2 E3 = (3 < n) ? __ldcs(ep + 3) : Z;

    for (int e = 0; e < n; e += 4) {
        const int2 N0 = (e + 4 < n) ? __ldcs(ep + e + 4) : Z;
        const int2 N1 = (e + 5 < n) ? __ldcs(ep + e + 5) : Z;
        const int2 N2 = (e + 6 < n) ? __ldcs(ep + e + 6) : Z;
        const int2 N3 = (e + 7 < n) ? __ldcs(ep + e + 7) : Z;
        const uint2 h0 = ((const uint2*)(g_h16 + (size_t)E0.x * CC))[lane];
        const uint2 h1 = ((const uint2*)(g_h16 + (size_t)E1.x * CC))[lane];
        const uint2 h2 = ((const uint2*)(g_h16 + (size_t)E2.x * CC))[lane];
        const uint2 h3 = ((const uint2*)(g_h16 + (size_t)E3.x * CC))[lane];
        gfma(acc, vs, E0, h0, lane); gfma(acc, vs, E1, h1, lane);
        gfma(acc, vs, E2, h2, lane); gfma(acc, vs, E3, h3, lane);
        E0 = N0; E1 = N1; E2 = N2; E3 = N3;
    }

    __half2 o0 = __floats2half2_rn(acc.x, acc.y);
    __half2 o1 = __floats2half2_rn(acc.z, acc.w);
    uint2 pk;
    pk.x = *(unsigned*)&o0;
    pk.y = *(unsigned*)&o1;
    ((uint2*)(g_out16 + (size_t)gw * CC))[lane] = pk;
    ((float4*)(g_vsum + (size_t)gw * CC))[lane] = vs;
}

// ---------------------------------------------------------------------------
// info_dot: g_info += sum_r dot(h32[r], vsum[r])  — pure streaming dot.
// ---------------------------------------------------------------------------
__global__ void info_dot_kernel() {
    __shared__ float red[256];
    const int tid = threadIdx.x;
    const size_t total4 = (size_t)BN * CC / 4;
    float p = 0.0f;
    for (size_t i = blockIdx.x * 256 + tid; i < total4; i += (size_t)gridDim.x * 256) {
        const float4 h = __ldcs(((const float4*)g_h32) + i);
        const float4 v = __ldcs(((const float4*)g_vsum) + i);
        p += h.x * v.x + h.y * v.y + h.z * v.z + h.w * v.w;
    }
    red[tid] = p;
    __syncthreads();
    for (int st = 128; st > 0; st >>= 1) {
        if (tid < st) red[tid] += red[tid + st];
        __syncthreads();
    }
    if (tid == 0 && red[0] != 0.0f) atomicAdd(&g_info, red[0]);
}

// ---------------------------------------------------------------------------
// finalize: out_scalar = (g_info + sum b_conv[col]*vq[b,m,e]) * wr
// ---------------------------------------------------------------------------
__global__ void finalize_kernel(const float* __restrict__ vq_grad,
                                const float* __restrict__ b_conv,
                                const float* __restrict__ wr_p,
                                float* __restrict__ out_scalar) {
    __shared__ float red[256];
    float s = 0.0f;
    for (int idx = threadIdx.x; idx < NBR * MM * DD; idx += 256) {
        const int b = idx >> 13;
        const int e = idx & 31;
        s += b_conv[b * DD + e] * vq_grad[idx];
    }
    red[threadIdx.x] = s;
    __syncthreads();
    for (int st = 128; st > 0; st >>= 1) {
        if (threadIdx.x < st) red[threadIdx.x] += red[threadIdx.x + st];
        __syncthreads();
    }
    if (threadIdx.x == 0) *out_scalar = (red[0] + g_info) * wr_p[0];
}

// ---------------------------------------------------------------------------
// y_kernel (WMMA): Y[r,c] = (out16 @ W16)[r,c] + b_fc[c] + X_B[r,c]
// ---------------------------------------------------------------------------
__global__ void y_kernel(const float* __restrict__ X,
                         const float* __restrict__ b_fc,
                         float* __restrict__ Y) {
    __shared__ __align__(16) char sraw[49152];
    __half* As = (__half*)sraw;                   // [64][128]
    __half* Bs = (__half*)(sraw + 16384);         // [128][128]
    float*  Ob = (float*)sraw;                    // [64][128] (after loop)

    const int row0 = blockIdx.x * YROWS;
    const int tid  = threadIdx.x;

    for (int i = tid; i < 1024; i += 256) {
        const int r = i >> 4, c16 = i & 15;
        const int row = row0 + r;
        uint4 v = make_uint4(0, 0, 0, 0);
        if (row < BN) v = ((const uint4*)(g_out16 + (size_t)row * CC))[c16];
        ((uint4*)As)[i] = v;
    }
    for (int i = tid; i < 2048; i += 256)
        ((uint4*)Bs)[i] = ((const uint4*)g_wfc16)[i];
    __syncthreads();

    const int w  = tid >> 5;
    const int rt = w >> 1;          // 0..3
    const int ch = w & 1;           // 0/1

    wmma::fragment<wmma::accumulator, 16, 16, 16, float> accf[4];
    #pragma unroll
    for (int t = 0; t < 4; t++) wmma::fill_fragment(accf[t], 0.0f);

    #pragma unroll
    for (int k = 0; k < 8; k++) {
        wmma::fragment<wmma::matrix_a, 16, 16, 16, __half, wmma::row_major> af;
        wmma::load_matrix_sync(af, As + (rt * 16) * CC + k * 16, CC);
        #pragma unroll
        for (int t = 0; t < 4; t++) {
            wmma::fragment<wmma::matrix_b, 16, 16, 16, __half, wmma::row_major> bf;
            wmma::load_matrix_sync(bf, Bs + (k * 16) * CC + ch * 64 + t * 16, CC);
            wmma::mma_sync(accf[t], af, bf, accf[t]);
        }
    }
    __syncthreads();   // done with As/Bs

    #pragma unroll
    for (int t = 0; t < 4; t++)
        wmma::store_matrix_sync(Ob + (rt * 16) * CC + ch * 64 + t * 16,
                                accf[t], CC, wmma::mem_row_major);
    __syncthreads();

    for (int i = tid; i < YROWS * 32; i += 256) {
        const int r = i >> 5, c4 = i & 31;
        const int row = row0 + r;
        if (row >= BN) continue;
        const float4 ov = ((const float4*)Ob)[r * 32 + c4];
        const float4 bv = ((const float4*)b_fc)[c4];
        const float4 xv = ((const float4*)(X + (size_t)row * CC))[c4];
        ((float4*)(Y + (size_t)row * CC))[c4] =
            make_float4(ov.x + bv.x + xv.x, ov.y + bv.y + xv.y,
                        ov.z + bv.z + xv.z, ov.w + bv.w + xv.w);
    }
}

// ---------------------------------------------------------------------------
extern "C" void kernel_launch(void* const* d_in, const int* in_sizes, int n_in,
                              void* d_out, int out_size) {
    const float* X_B      = (const float*)d_in[0];
    const int*   esrc_bb  = (const int*)  d_in[1];
    const int*   edst_bb  = (const int*)  d_in[2];
    const float* ew_bb    = (const float*)d_in[3];
    const int*   esrc_bm  = (const int*)  d_in[4];
    const int*   edst_bm  = (const int*)  d_in[5];
    const float* ew_bm    = (const float*)d_in[6];
    const int*   c_idx    = (const int*)  d_in[7];
    const float* wr       = (const float*)d_in[8];
    const float* codebook = (const float*)d_in[9];
    const float* vq_grad  = (const float*)d_in[10];
    const float* W_conv   = (const float*)d_in[11];
    const float* b_conv   = (const float*)d_in[12];
    const float* W_fc     = (const float*)d_in[13];
    const float* b_fc     = (const float*)d_in[14];
    float* out = (float*)d_out;

    const int Ebb  = in_sizes[1];
    const int Ebm  = in_sizes[4];
    const int Etot = Ebb + Ebm;

    prep_a_kernel<<<(BN + 255) / 256, 256>>>();                            // 1
    prep_b_kernel<<<(NBR * MM * DD + 255) / 256, 256>>>(vq_grad, W_fc);    // 2
    compute_h_kernel<<<(NODES + HROWS - 1) / HROWS, 256>>>(X_B, codebook,  // 3
                                                           W_conv, wr);
    fill_dst_kernel<<<(Etot + 255) / 256, 256>>>(esrc_bb, edst_bb, ew_bb,  // 4 <- profiled
                                                 esrc_bm, edst_bm, ew_bm,
                                                 c_idx, Ebb, Etot);
    gather_kernel<<<(BN * 32 + 255) / 256, 256>>>(b_conv);                 // 5
    info_dot_kernel<<<1184, 256>>>();                                      // 6
    finalize_kernel<<<1, 256>>>(vq_grad, b_conv, wr, out + (out_size - 1));// 7
    y_kernel<<<(BN + YROWS - 1) / YROWS, 256>>>(X_B, b_fc, out);           // 8
}

// round 14
// speedup vs baseline: 1.2212x; 1.0131x over previous
#include <cuda_runtime.h>
#include <cuda_fp16.h>
#include <mma.h>
#include <cstdint>

using namespace nvcuda;

#define BN     50000
#define NBR    4
#define DD     32
#define CC     128          // NBR*DD
#define MM     256
#define NODES  (BN + MM)    // 50256
#define CAPR   128          // per-batch-row bucket capacity (mean ~40)
#define CSTR   8            // counter stride (ints) -> 32B, no LTS false sharing
#define YROWS  64           // rows per y block

// scratch (static device globals — no allocation)
__device__ __half g_x16[(size_t)NODES * CC];   // 12.9MB X_in in fp16 (gather src)
__device__ __half g_xagg16[(size_t)BN * CC];   // aggregation result (y input)
__device__ __half g_wp16[CC * CC];             // W' = blockdiag(W_conv)@W_fc, fp16
__device__ float  g_bp[CC];                    // b'  = b_conv@W_fc + b_fc
__device__ int    g_cnt[BN * CSTR];            // padded counters (32B apart)
__device__ int2   g_ent[(size_t)BN * CAPR];    // (src_row, w_bits) per batch-dst
__device__ float  g_vq32r[MM * CC];            // vq_grad re-laid [m][b*32+e]
__device__ float  g_vqp[MM * CC];              // vq' = vq @ Wblk^T (128KB, L1-hot)
__device__ float  g_vsum[(size_t)BN * CC];     // per-row sum w*vq' (fp32)
__device__ float  g_info;

// ---------------------------------------------------------------------------
// prep_x: x16 rows (X for batch, codebook*wr for codewords) + zero counters
// + relayout vq_grad [b][m][e] -> [m][b*32+e].
// ---------------------------------------------------------------------------
__global__ void prep_x_kernel(const float* __restrict__ X,
                              const float* __restrict__ codebook,
                              const float* __restrict__ vq_grad,
                              const float* __restrict__ wr_p) {
    const int idx = blockIdx.x * blockDim.x + threadIdx.x;   // NODES*64 half2 units
    if (idx < NODES * 64) {
        const int row = idx >> 6;
        const int c2  = idx & 63;           // half2 column (0..63)
        float2 v;
        if (row < BN) {
            v = ((const float2*)X)[(size_t)row * 64 + c2];
        } else {
            const float wr = wr_p[0];
            const int b = c2 >> 4, sub = c2 & 15, m = row - BN;
            v = ((const float2*)codebook)[((size_t)b * MM + m) * 16 + sub];
            v.x *= wr; v.y *= wr;
        }
        ((__half2*)g_x16)[idx] = __floats2half2_rn(v.x, v.y);
    }
    if (idx < NBR * MM * DD) {
        const int b = idx >> 13;
        const int m = (idx >> 5) & (MM - 1);
        const int e = idx & 31;
        g_vq32r[m * CC + b * DD + e] = vq_grad[idx];
    }
    if (idx < BN) g_cnt[idx * CSTR] = 0;
    if (idx == 0) g_info = 0.0f;
}

// ---------------------------------------------------------------------------
// prep_w: block 0..127   -> W'[k][*]  (k = b*32+d): sum_e Wconv[b][d][e]*W_fc[b*32+e][*]
//         block 128      -> b'[*] = sum_k b_conv[k]*W_fc[k][*] + b_fc[*]
//         block 129..384 -> vq'[m][*] (m = blk-129): sum_e Wconv[b][d][e]*vq32r[m][b*32+e]
// 128 threads per block (one output column / one k).
// ---------------------------------------------------------------------------
__global__ void prep_w_kernel(const float* __restrict__ W_conv,
                              const float* __restrict__ W_fc,
                              const float* __restrict__ b_conv,
                              const float* __restrict__ b_fc) {
    const int t = threadIdx.x;              // 0..127
    const int blk = blockIdx.x;
    if (blk < CC) {
        // W'[k=blk][c=t]
        const int b = blk >> 5, d = blk & 31;
        const float* wrow = W_conv + (b * DD + d) * DD;   // [e]
        float s = 0.0f;
        #pragma unroll
        for (int e = 0; e < DD; e++)
            s = fmaf(wrow[e], W_fc[(b * DD + e) * CC + t], s);
        g_wp16[blk * CC + t] = __float2half_rn(s);
    } else if (blk == CC) {
        // b'[c=t]
        float s = b_fc[t];
        for (int k = 0; k < CC; k++)
            s = fmaf(b_conv[k], W_fc[k * CC + t], s);
        g_bp[t] = s;
    } else {
        // vq'[m][k=t],  k = b*32+d
        const int m = blk - CC - 1;
        const int b = t >> 5, d = t & 31;
        const float* wrow = W_conv + (b * DD + d) * DD;   // [e]
        const float* vrow = g_vq32r + m * CC + b * DD;    // [e]
        float s = 0.0f;
        #pragma unroll
        for (int e = 0; e < DD; e++)
            s = fmaf(wrow[e], vrow[e], s);
        g_vqp[m * CC + t] = s;
    }
}

// ---------------------------------------------------------------------------
// fill: bucket edges by dst batch row (padded counters).
// ---------------------------------------------------------------------------
__global__ void fill_dst_kernel(const int* __restrict__ sbb, const int* __restrict__ dbb,
                                const float* __restrict__ wbb,
                                const int* __restrict__ sbm, const int* __restrict__ dbm,
                                const float* __restrict__ wbm,
                                const int* __restrict__ cidx, int Ebb, int Etot) {
    const int i = blockIdx.x * blockDim.x + threadIdx.x;
    if (i >= Etot) return;
    int r, s; float w;
    if (i < Ebb) { r = dbb[i]; s = sbb[i]; w = wbb[i]; }
    else { const int j = i - Ebb; r = dbm[j]; s = BN + cidx[sbm[j]]; w = wbm[j]; }
    const int pos = atomicAdd(&g_cnt[r * CSTR], 1);
    if (pos < CAPR)
        g_ent[(size_t)r * CAPR + pos] = make_int2(s, __float_as_int(w));
}

// ---------------------------------------------------------------------------
// gather (4th launch -> profiled): single bucket walk per row produces BOTH
//   xagg16[r] = fp16(sum w * x16[src])            (fp32 accumulate)
//   vsum[r]   = sum_{src>=BN} w * vq'[src-BN]     (fp32, info path)
// ---------------------------------------------------------------------------
__device__ __forceinline__ void gfma(float4& acc, float4& vs, int2 E, uint2 hv,
                                     int lane) {
    const float w = __int_as_float(E.y);
    const float2 f0 = __half22float2(*(const __half2*)&hv.x);
    const float2 f1 = __half22float2(*(const __half2*)&hv.y);
    acc.x = fmaf(w, f0.x, acc.x); acc.y = fmaf(w, f0.y, acc.y);
    acc.z = fmaf(w, f1.x, acc.z); acc.w = fmaf(w, f1.y, acc.w);
    if (E.x >= BN) {   // warp-uniform
        const float4 qv = ((const float4*)(g_vqp + (size_t)(E.x - BN) * CC))[lane];
        vs.x = fmaf(w, qv.x, vs.x); vs.y = fmaf(w, qv.y, vs.y);
        vs.z = fmaf(w, qv.z, vs.z); vs.w = fmaf(w, qv.w, vs.w);
    }
}

__global__ void gather_kernel() {
    const int gw   = (blockIdx.x * blockDim.x + threadIdx.x) >> 5;
    const int lane = threadIdx.x & 31;
    if (gw >= BN) return;
    int n = g_cnt[gw * CSTR]; if (n > CAPR) n = CAPR;

    float4 acc = make_float4(0.f, 0.f, 0.f, 0.f);
    float4 vs  = make_float4(0.f, 0.f, 0.f, 0.f);
    const int2* ep = g_ent + (size_t)gw * CAPR;
    const int2 Z = make_int2(0, 0);   // src 0 (<BN), w == 0.0f

    int2 E0 = (0 < n) ? __ldcs(ep + 0) : Z;
    int2 E1 = (1 < n) ? __ldcs(ep + 1) : Z;
    int2 E2 = (2 < n) ? __ldcs(ep + 2) : Z;
    int2 E3 = (3 < n) ? __ldcs(ep + 3) : Z;

    for (int e = 0; e < n; e += 4) {
        const int2 N0 = (e + 4 < n) ? __ldcs(ep + e + 4) : Z;
        const int2 N1 = (e + 5 < n) ? __ldcs(ep + e + 5) : Z;
        const int2 N2 = (e + 6 < n) ? __ldcs(ep + e + 6) : Z;
        const int2 N3 = (e + 7 < n) ? __ldcs(ep + e + 7) : Z;
        const uint2 h0 = ((const uint2*)(g_x16 + (size_t)E0.x * CC))[lane];
        const uint2 h1 = ((const uint2*)(g_x16 + (size_t)E1.x * CC))[lane];
        const uint2 h2 = ((const uint2*)(g_x16 + (size_t)E2.x * CC))[lane];
        const uint2 h3 = ((const uint2*)(g_x16 + (size_t)E3.x * CC))[lane];
        gfma(acc, vs, E0, h0, lane); gfma(acc, vs, E1, h1, lane);
        gfma(acc, vs, E2, h2, lane); gfma(acc, vs, E3, h3, lane);
        E0 = N0; E1 = N1; E2 = N2; E3 = N3;
    }

    __half2 o0 = __floats2half2_rn(acc.x, acc.y);
    __half2 o1 = __floats2half2_rn(acc.z, acc.w);
    uint2 pk;
    pk.x = *(unsigned*)&o0;
    pk.y = *(unsigned*)&o1;
    ((uint2*)(g_xagg16 + (size_t)gw * CC))[lane] = pk;
    ((float4*)(g_vsum + (size_t)gw * CC))[lane] = vs;
}

// ---------------------------------------------------------------------------
// info_dot: g_info += sum_r dot(X_B[r], vsum[r])  — pure streaming dot (exact).
// ---------------------------------------------------------------------------
__global__ void info_dot_kernel(const float* __restrict__ X) {
    __shared__ float red[256];
    const int tid = threadIdx.x;
    const size_t total4 = (size_t)BN * CC / 4;
    float p = 0.0f;
    for (size_t i = blockIdx.x * 256 + tid; i < total4; i += (size_t)gridDim.x * 256) {
        const float4 h = __ldcs(((const float4*)X) + i);
        const float4 v = __ldcs(((const float4*)g_vsum) + i);
        p += h.x * v.x + h.y * v.y + h.z * v.z + h.w * v.w;
    }
    red[tid] = p;
    __syncthreads();
    for (int st = 128; st > 0; st >>= 1) {
        if (tid < st) red[tid] += red[tid + st];
        __syncthreads();
    }
    if (tid == 0 && red[0] != 0.0f) atomicAdd(&g_info, red[0]);
}

// ---------------------------------------------------------------------------
// finalize: out_scalar = (g_info + sum b_conv[col]*vq[b,m,e]) * wr
// ---------------------------------------------------------------------------
__global__ void finalize_kernel(const float* __restrict__ vq_grad,
                                const float* __restrict__ b_conv,
                                const float* __restrict__ wr_p,
                                float* __restrict__ out_scalar) {
    __shared__ float red[256];
    float s = 0.0f;
    for (int idx = threadIdx.x; idx < NBR * MM * DD; idx += 256) {
        const int b = idx >> 13;
        const int e = idx & 31;
        s += b_conv[b * DD + e] * vq_grad[idx];
    }
    red[threadIdx.x] = s;
    __syncthreads();
    for (int st = 128; st > 0; st >>= 1) {
        if (threadIdx.x < st) red[threadIdx.x] += red[threadIdx.x + st];
        __syncthreads();
    }
    if (threadIdx.x == 0) *out_scalar = (red[0] + g_info) * wr_p[0];
}

// ---------------------------------------------------------------------------
// y_kernel (WMMA): Y[r,c] = (xagg16 @ W'16)[r,c] + b'[c] + X_B[r,c]
// ---------------------------------------------------------------------------
__global__ void y_kernel(const float* __restrict__ X,
                         float* __restrict__ Y) {
    __shared__ __align__(16) char sraw[49152];
    __half* As = (__half*)sraw;                   // [64][128]
    __half* Bs = (__half*)(sraw + 16384);         // [128][128]
    float*  Ob = (float*)sraw;                    // [64][128] (after loop)

    const int row0 = blockIdx.x * YROWS;
    const int tid  = threadIdx.x;

    for (int i = tid; i < 1024; i += 256) {
        const int r = i >> 4, c16 = i & 15;
        const int row = row0 + r;
        uint4 v = make_uint4(0, 0, 0, 0);
        if (row < BN) v = ((const uint4*)(g_xagg16 + (size_t)row * CC))[c16];
        ((uint4*)As)[i] = v;
    }
    for (int i = tid; i < 2048; i += 256)
        ((uint4*)Bs)[i] = ((const uint4*)g_wp16)[i];
    __syncthreads();

    const int w  = tid >> 5;
    const int rt = w >> 1;          // 0..3
    const int ch = w & 1;           // 0/1

    wmma::fragment<wmma::accumulator, 16, 16, 16, float> accf[4];
    #pragma unroll
    for (int t = 0; t < 4; t++) wmma::fill_fragment(accf[t], 0.0f);

    #pragma unroll
    for (int k = 0; k < 8; k++) {
        wmma::fragment<wmma::matrix_a, 16, 16, 16, __half, wmma::row_major> af;
        wmma::load_matrix_sync(af, As + (rt * 16) * CC + k * 16, CC);
        #pragma unroll
        for (int t = 0; t < 4; t++) {
            wmma::fragment<wmma::matrix_b, 16, 16, 16, __half, wmma::row_major> bf;
            wmma::load_matrix_sync(bf, Bs + (k * 16) * CC + ch * 64 + t * 16, CC);
            wmma::mma_sync(accf[t], af, bf, accf[t]);
        }
    }
    __syncthreads();   // done with As/Bs

    #pragma unroll
    for (int t = 0; t < 4; t++)
        wmma::store_matrix_sync(Ob + (rt * 16) * CC + ch * 64 + t * 16,
                                accf[t], CC, wmma::mem_row_major);
    __syncthreads();

    for (int i = tid; i < YROWS * 32; i += 256) {
        const int r = i >> 5, c4 = i & 31;
        const int row = row0 + r;
        if (row >= BN) continue;
        const float4 ov = ((const float4*)Ob)[r * 32 + c4];
        const float4 bv = ((const float4*)g_bp)[c4];
        const float4 xv = ((const float4*)(X + (size_t)row * CC))[c4];
        ((float4*)(Y + (size_t)row * CC))[c4] =
            make_float4(ov.x + bv.x + xv.x, ov.y + bv.y + xv.y,
                        ov.z + bv.z + xv.z, ov.w + bv.w + xv.w);
    }
}

// ---------------------------------------------------------------------------
extern "C" void kernel_launch(void* const* d_in, const int* in_sizes, int n_in,
                              void* d_out, int out_size) {
    const float* X_B      = (const float*)d_in[0];
    const int*   esrc_bb  = (const int*)  d_in[1];
    const int*   edst_bb  = (const int*)  d_in[2];
    const float* ew_bb    = (const float*)d_in[3];
    const int*   esrc_bm  = (const int*)  d_in[4];
    const int*   edst_bm  = (const int*)  d_in[5];
    const float* ew_bm    = (const float*)d_in[6];
    const int*   c_idx    = (const int*)  d_in[7];
    const float* wr       = (const float*)d_in[8];
    const float* codebook = (const float*)d_in[9];
    const float* vq_grad  = (const float*)d_in[10];
    const float* W_conv   = (const float*)d_in[11];
    const float* b_conv   = (const float*)d_in[12];
    const float* W_fc     = (const float*)d_in[13];
    const float* b_fc     = (const float*)d_in[14];
    float* out = (float*)d_out;

    const int Ebb  = in_sizes[1];
    const int Ebm  = in_sizes[4];
    const int Etot = Ebb + Ebm;

    prep_x_kernel<<<(NODES * 64 + 255) / 256, 256>>>(X_B, codebook,        // 1
                                                     vq_grad, wr);
    prep_w_kernel<<<CC + 1 + MM, 128>>>(W_conv, W_fc, b_conv, b_fc);       // 2
    fill_dst_kernel<<<(Etot + 255) / 256, 256>>>(esrc_bb, edst_bb, ew_bb,  // 3
                                                 esrc_bm, edst_bm, ew_bm,
                                                 c_idx, Ebb, Etot);
    gather_kernel<<<(BN * 32 + 255) / 256, 256>>>();                       // 4 <- profiled
    info_dot_kernel<<<1184, 256>>>(X_B);                                   // 5
    finalize_kernel<<<1, 256>>>(vq_grad, b_conv, wr, out + (out_size - 1));// 6
    y_kernel<<<(BN + YROWS - 1) / YROWS, 256>>>(X_B, out);                 // 7
}

// round 15
// speedup vs baseline: 1.2711x; 1.0409x over previous
#include <cuda_runtime.h>
#include <cuda_fp16.h>
#include <mma.h>
#include <cstdint>

using namespace nvcuda;

#define BN     50000
#define NBR    4
#define DD     32
#define CC     128          // NBR*DD
#define MM     256
#define NODES  (BN + MM)    // 50256
#define CAPB   64           // per-type bucket capacity (mean ~20)
#define CSTR   8            // counter stride (ints) -> 32B, no LTS false sharing
#define YROWS  64           // rows per y block

// scratch (static device globals — no allocation)
__device__ __half g_x16[(size_t)NODES * CC];   // 12.9MB X_in fp16 (gather src)
__device__ __half g_xagg16[(size_t)BN * CC];   // aggregation result (y input)
__device__ __half g_wp16[CC * CC];             // W' = blockdiag(W_conv)@W_fc, fp16
__device__ float  g_bp[CC];                    // b'  = b_conv@W_fc + b_fc
__device__ int    g_cntA[BN * CSTR];           // bb counters (32B apart)
__device__ int    g_cntB[BN * CSTR];           // bm counters (32B apart)
__device__ int2   g_entA[(size_t)BN * CAPB];   // bb: (x_byte_off, w_bits)
__device__ int2   g_entB[(size_t)BN * CAPB];   // bm: (vq_byte_off = m*512, w_bits)
__device__ float  g_vq32r[MM * CC];            // vq_grad re-laid [m][b*32+e]
__device__ float  g_vqp[MM * CC];              // vq' = vq @ Wblk^T (128KB, L1-hot)
__device__ float  g_vsum[(size_t)BN * CC];     // per-row sum w*vq' (fp32)
__device__ float  g_info;

// ---------------------------------------------------------------------------
// prep_x: x16 rows (X for batch, codebook*wr for codewords) + zero counters
// + relayout vq_grad [b][m][e] -> [m][b*32+e].
// ---------------------------------------------------------------------------
__global__ void prep_x_kernel(const float* __restrict__ X,
                              const float* __restrict__ codebook,
                              const float* __restrict__ vq_grad,
                              const float* __restrict__ wr_p) {
    const int idx = blockIdx.x * blockDim.x + threadIdx.x;   // NODES*64 half2 units
    if (idx < NODES * 64) {
        const int row = idx >> 6;
        const int c2  = idx & 63;           // half2 column (0..63)
        float2 v;
        if (row < BN) {
            v = ((const float2*)X)[(size_t)row * 64 + c2];
        } else {
            const float wr = wr_p[0];
            const int b = c2 >> 4, sub = c2 & 15, m = row - BN;
            v = ((const float2*)codebook)[((size_t)b * MM + m) * 16 + sub];
            v.x *= wr; v.y *= wr;
        }
        ((__half2*)g_x16)[idx] = __floats2half2_rn(v.x, v.y);
    }
    if (idx < NBR * MM * DD) {
        const int b = idx >> 13;
        const int m = (idx >> 5) & (MM - 1);
        const int e = idx & 31;
        g_vq32r[m * CC + b * DD + e] = vq_grad[idx];
    }
    if (idx < BN) { g_cntA[idx * CSTR] = 0; g_cntB[idx * CSTR] = 0; }
    if (idx == 0) g_info = 0.0f;
}

// ---------------------------------------------------------------------------
// prep_w: block 0..127   -> W'[k][*]; block 128 -> b'; block 129.. -> vq'[m][*]
// ---------------------------------------------------------------------------
__global__ void prep_w_kernel(const float* __restrict__ W_conv,
                              const float* __restrict__ W_fc,
                              const float* __restrict__ b_conv,
                              const float* __restrict__ b_fc) {
    const int t = threadIdx.x;              // 0..127
    const int blk = blockIdx.x;
    if (blk < CC) {
        const int b = blk >> 5, d = blk & 31;
        const float* wrow = W_conv + (b * DD + d) * DD;   // [e]
        float s = 0.0f;
        #pragma unroll
        for (int e = 0; e < DD; e++)
            s = fmaf(wrow[e], W_fc[(b * DD + e) * CC + t], s);
        g_wp16[blk * CC + t] = __float2half_rn(s);
    } else if (blk == CC) {
        float s = b_fc[t];
        for (int k = 0; k < CC; k++)
            s = fmaf(b_conv[k], W_fc[k * CC + t], s);
        g_bp[t] = s;
    } else {
        const int m = blk - CC - 1;
        const int b = t >> 5, d = t & 31;
        const float* wrow = W_conv + (b * DD + d) * DD;   // [e]
        const float* vrow = g_vq32r + m * CC + b * DD;    // [e]
        float s = 0.0f;
        #pragma unroll
        for (int e = 0; e < DD; e++)
            s = fmaf(wrow[e], vrow[e], s);
        g_vqp[m * CC + t] = s;
    }
}

// ---------------------------------------------------------------------------
// fill: dual buckets. bb edges -> entA (x byte offset = src*256);
//       bm edges -> entB (vq byte offset = c_indices[src]*512).
// ---------------------------------------------------------------------------
__global__ void fill_dst_kernel(const int* __restrict__ sbb, const int* __restrict__ dbb,
                                const float* __restrict__ wbb,
                                const int* __restrict__ sbm, const int* __restrict__ dbm,
                                const float* __restrict__ wbm,
                                const int* __restrict__ cidx, int Ebb, int Etot) {
    const int i = blockIdx.x * blockDim.x + threadIdx.x;
    if (i >= Etot) return;
    if (i < Ebb) {
        const int r = dbb[i];
        const int off = sbb[i] << 8;            // *256 bytes (fp16 row)
        const float w = wbb[i];
        const int pos = atomicAdd(&g_cntA[r * CSTR], 1);
        if (pos < CAPB)
            g_entA[(size_t)r * CAPB + pos] = make_int2(off, __float_as_int(w));
    } else {
        const int j = i - Ebb;
        const int r = dbm[j];
        const int off = cidx[sbm[j]] << 9;      // m*512 bytes (fp32 vq' row)
        const float w = wbm[j];
        const int pos = atomicAdd(&g_cntB[r * CSTR], 1);
        if (pos < CAPB)
            g_entB[(size_t)r * CAPB + pos] = make_int2(off, __float_as_int(w));
    }
}

// ---------------------------------------------------------------------------
// gather (4th launch -> profiled): two branch-free loops per row.
//   loop A (bb): acc += w * x16[src]                 (x-FMA only)
//   loop B (bm): acc += w * x16[BN+m]; vs += w*vq'[m] (both, unconditional)
// fp32 accumulate; writes xagg16 + vsum.
// ---------------------------------------------------------------------------
__device__ __forceinline__ void xfma(float4& acc, float w, uint2 hv) {
    const float2 f0 = __half22float2(*(const __half2*)&hv.x);
    const float2 f1 = __half22float2(*(const __half2*)&hv.y);
    acc.x = fmaf(w, f0.x, acc.x); acc.y = fmaf(w, f0.y, acc.y);
    acc.z = fmaf(w, f1.x, acc.z); acc.w = fmaf(w, f1.y, acc.w);
}

__global__ void gather_kernel() {
    const int gw   = (blockIdx.x * blockDim.x + threadIdx.x) >> 5;
    const int lane = threadIdx.x & 31;
    if (gw >= BN) return;

    float4 acc = make_float4(0.f, 0.f, 0.f, 0.f);
    float4 vs  = make_float4(0.f, 0.f, 0.f, 0.f);
    const int2 Z = make_int2(0, 0);             // offset 0, w == 0.0f
    const char* xb = (const char*)g_x16 + (size_t)lane * 8;

    // ---- loop A: bb edges (x only) ----
    {
        int n = g_cntA[gw * CSTR]; if (n > CAPB) n = CAPB;
        const int2* ep = g_entA + (size_t)gw * CAPB;
        int2 E0 = (0 < n) ? __ldcs(ep + 0) : Z;
        int2 E1 = (1 < n) ? __ldcs(ep + 1) : Z;
        int2 E2 = (2 < n) ? __ldcs(ep + 2) : Z;
        int2 E3 = (3 < n) ? __ldcs(ep + 3) : Z;
        for (int e = 0; e < n; e += 4) {
            const int2 N0 = (e + 4 < n) ? __ldcs(ep + e + 4) : Z;
            const int2 N1 = (e + 5 < n) ? __ldcs(ep + e + 5) : Z;
            const int2 N2 = (e + 6 < n) ? __ldcs(ep + e + 6) : Z;
            const int2 N3 = (e + 7 < n) ? __ldcs(ep + e + 7) : Z;
            const uint2 h0 = *(const uint2*)(xb + E0.x);
            const uint2 h1 = *(const uint2*)(xb + E1.x);
            const uint2 h2 = *(const uint2*)(xb + E2.x);
            const uint2 h3 = *(const uint2*)(xb + E3.x);
            xfma(acc, __int_as_float(E0.y), h0);
            xfma(acc, __int_as_float(E1.y), h1);
            xfma(acc, __int_as_float(E2.y), h2);
            xfma(acc, __int_as_float(E3.y), h3);
            E0 = N0; E1 = N1; E2 = N2; E3 = N3;
        }
    }

    // ---- loop B: bm edges (x + vq, unconditional) ----
    {
        int n = g_cntB[gw * CSTR]; if (n > CAPB) n = CAPB;
        const int2* ep = g_entB + (size_t)gw * CAPB;
        const char* xcw = (const char*)g_x16 + (size_t)BN * 256 + (size_t)lane * 8;
        const char* qb  = (const char*)g_vqp + (size_t)lane * 16;
        int2 E0 = (0 < n) ? __ldcs(ep + 0) : Z;
        int2 E1 = (1 < n) ? __ldcs(ep + 1) : Z;
        int2 E2 = (2 < n) ? __ldcs(ep + 2) : Z;
        int2 E3 = (3 < n) ? __ldcs(ep + 3) : Z;
        for (int e = 0; e < n; e += 4) {
            const int2 N0 = (e + 4 < n) ? __ldcs(ep + e + 4) : Z;
            const int2 N1 = (e + 5 < n) ? __ldcs(ep + e + 5) : Z;
            const int2 N2 = (e + 6 < n) ? __ldcs(ep + e + 6) : Z;
            const int2 N3 = (e + 7 < n) ? __ldcs(ep + e + 7) : Z;
            const uint2 h0 = *(const uint2*)(xcw + (E0.x >> 1));
            const uint2 h1 = *(const uint2*)(xcw + (E1.x >> 1));
            const uint2 h2 = *(const uint2*)(xcw + (E2.x >> 1));
            const uint2 h3 = *(const uint2*)(xcw + (E3.x >> 1));
            const float4 q0 = *(const float4*)(qb + E0.x);
            const float4 q1 = *(const float4*)(qb + E1.x);
            const float4 q2 = *(const float4*)(qb + E2.x);
            const float4 q3 = *(const float4*)(qb + E3.x);
            const float w0 = __int_as_float(E0.y);
            const float w1 = __int_as_float(E1.y);
            const float w2 = __int_as_float(E2.y);
            const float w3 = __int_as_float(E3.y);
            xfma(acc, w0, h0); xfma(acc, w1, h1);
            xfma(acc, w2, h2); xfma(acc, w3, h3);
            vs.x = fmaf(w0, q0.x, vs.x); vs.y = fmaf(w0, q0.y, vs.y);
            vs.z = fmaf(w0, q0.z, vs.z); vs.w = fmaf(w0, q0.w, vs.w);
            vs.x = fmaf(w1, q1.x, vs.x); vs.y = fmaf(w1, q1.y, vs.y);
            vs.z = fmaf(w1, q1.z, vs.z); vs.w = fmaf(w1, q1.w, vs.w);
            vs.x = fmaf(w2, q2.x, vs.x); vs.y = fmaf(w2, q2.y, vs.y);
            vs.z = fmaf(w2, q2.z, vs.z); vs.w = fmaf(w2, q2.w, vs.w);
            vs.x = fmaf(w3, q3.x, vs.x); vs.y = fmaf(w3, q3.y, vs.y);
            vs.z = fmaf(w3, q3.z, vs.z); vs.w = fmaf(w3, q3.w, vs.w);
            E0 = N0; E1 = N1; E2 = N2; E3 = N3;
        }
    }

    __half2 o0 = __floats2half2_rn(acc.x, acc.y);
    __half2 o1 = __floats2half2_rn(acc.z, acc.w);
    uint2 pk;
    pk.x = *(unsigned*)&o0;
    pk.y = *(unsigned*)&o1;
    ((uint2*)(g_xagg16 + (size_t)gw * CC))[lane] = pk;
    ((float4*)(g_vsum + (size_t)gw * CC))[lane] = vs;
}

// ---------------------------------------------------------------------------
// info_dot: g_info += sum_r dot(X_B[r], vsum[r])  — pure streaming dot (exact).
// ---------------------------------------------------------------------------
__global__ void info_dot_kernel(const float* __restrict__ X) {
    __shared__ float red[256];
    const int tid = threadIdx.x;
    const size_t total4 = (size_t)BN * CC / 4;
    float p = 0.0f;
    for (size_t i = blockIdx.x * 256 + tid; i < total4; i += (size_t)gridDim.x * 256) {
        const float4 h = __ldcs(((const float4*)X) + i);
        const float4 v = __ldcs(((const float4*)g_vsum) + i);
        p += h.x * v.x + h.y * v.y + h.z * v.z + h.w * v.w;
    }
    red[tid] = p;
    __syncthreads();
    for (int st = 128; st > 0; st >>= 1) {
        if (tid < st) red[tid] += red[tid + st];
        __syncthreads();
    }
    if (tid == 0 && red[0] != 0.0f) atomicAdd(&g_info, red[0]);
}

// ---------------------------------------------------------------------------
// finalize: out_scalar = (g_info + sum b_conv[col]*vq[b,m,e]) * wr
// ---------------------------------------------------------------------------
__global__ void finalize_kernel(const float* __restrict__ vq_grad,
                                const float* __restrict__ b_conv,
                                const float* __restrict__ wr_p,
                                float* __restrict__ out_scalar) {
    __shared__ float red[256];
    float s = 0.0f;
    for (int idx = threadIdx.x; idx < NBR * MM * DD; idx += 256) {
        const int b = idx >> 13;
        const int e = idx & 31;
        s += b_conv[b * DD + e] * vq_grad[idx];
    }
    red[threadIdx.x] = s;
    __syncthreads();
    for (int st = 128; st > 0; st >>= 1) {
        if (threadIdx.x < st) red[threadIdx.x] += red[threadIdx.x + st];
        __syncthreads();
    }
    if (threadIdx.x == 0) *out_scalar = (red[0] + g_info) * wr_p[0];
}

// ---------------------------------------------------------------------------
// y_kernel (WMMA): Y[r,c] = (xagg16 @ W'16)[r,c] + b'[c] + X_B[r,c]
// ---------------------------------------------------------------------------
__global__ void y_kernel(const float* __restrict__ X,
                         float* __restrict__ Y) {
    __shared__ __align__(16) char sraw[49152];
    __half* As = (__half*)sraw;                   // [64][128]
    __half* Bs = (__half*)(sraw + 16384);         // [128][128]
    float*  Ob = (float*)sraw;                    // [64][128] (after loop)

    const int row0 = blockIdx.x * YROWS;
    const int tid  = threadIdx.x;

    for (int i = tid; i < 1024; i += 256) {
        const int r = i >> 4, c16 = i & 15;
        const int row = row0 + r;
        uint4 v = make_uint4(0, 0, 0, 0);
        if (row < BN) v = ((const uint4*)(g_xagg16 + (size_t)row * CC))[c16];
        ((uint4*)As)[i] = v;
    }
    for (int i = tid; i < 2048; i += 256)
        ((uint4*)Bs)[i] = ((const uint4*)g_wp16)[i];
    __syncthreads();

    const int w  = tid >> 5;
    const int rt = w >> 1;          // 0..3
    const int ch = w & 1;           // 0/1

    wmma::fragment<wmma::accumulator, 16, 16, 16, float> accf[4];
    #pragma unroll
    for (int t = 0; t < 4; t++) wmma::fill_fragment(accf[t], 0.0f);

    #pragma unroll
    for (int k = 0; k < 8; k++) {
        wmma::fragment<wmma::matrix_a, 16, 16, 16, __half, wmma::row_major> af;
        wmma::load_matrix_sync(af, As + (rt * 16) * CC + k * 16, CC);
        #pragma unroll
        for (int t = 0; t < 4; t++) {
            wmma::fragment<wmma::matrix_b, 16, 16, 16, __half, wmma::row_major> bf;
            wmma::load_matrix_sync(bf, Bs + (k * 16) * CC + ch * 64 + t * 16, CC);
            wmma::mma_sync(accf[t], af, bf, accf[t]);
        }
    }
    __syncthreads();   // done with As/Bs

    #pragma unroll
    for (int t = 0; t < 4; t++)
        wmma::store_matrix_sync(Ob + (rt * 16) * CC + ch * 64 + t * 16,
                                accf[t], CC, wmma::mem_row_major);
    __syncthreads();

    for (int i = tid; i < YROWS * 32; i += 256) {
        const int r = i >> 5, c4 = i & 31;
        const int row = row0 + r;
        if (row >= BN) continue;
        const float4 ov = ((const float4*)Ob)[r * 32 + c4];
        const float4 bv = ((const float4*)g_bp)[c4];
        const float4 xv = ((const float4*)(X + (size_t)row * CC))[c4];
        ((float4*)(Y + (size_t)row * CC))[c4] =
            make_float4(ov.x + bv.x + xv.x, ov.y + bv.y + xv.y,
                        ov.z + bv.z + xv.z, ov.w + bv.w + xv.w);
    }
}

// ---------------------------------------------------------------------------
extern "C" void kernel_launch(void* const* d_in, const int* in_sizes, int n_in,
                              void* d_out, int out_size) {
    const float* X_B      = (const float*)d_in[0];
    const int*   esrc_bb  = (const int*)  d_in[1];
    const int*   edst_bb  = (const int*)  d_in[2];
    const float* ew_bb    = (const float*)d_in[3];
    const int*   esrc_bm  = (const int*)  d_in[4];
    const int*   edst_bm  = (const int*)  d_in[5];
    const float* ew_bm    = (const float*)d_in[6];
    const int*   c_idx    = (const int*)  d_in[7];
    const float* wr       = (const float*)d_in[8];
    const float* codebook = (const float*)d_in[9];
    const float* vq_grad  = (const float*)d_in[10];
    const float* W_conv   = (const float*)d_in[11];
    const float* b_conv   = (const float*)d_in[12];
    const float* W_fc     = (const float*)d_in[13];
    const float* b_fc     = (const float*)d_in[14];
    float* out = (float*)d_out;

    const int Ebb  = in_sizes[1];
    const int Ebm  = in_sizes[4];
    const int Etot = Ebb + Ebm;

    prep_x_kernel<<<(NODES * 64 + 255) / 256, 256>>>(X_B, codebook,        // 1
                                                     vq_grad, wr);
    prep_w_kernel<<<CC + 1 + MM, 128>>>(W_conv, W_fc, b_conv, b_fc);       // 2
    fill_dst_kernel<<<(Etot + 255) / 256, 256>>>(esrc_bb, edst_bb, ew_bb,  // 3
                                                 esrc_bm, edst_bm, ew_bm,
                                                 c_idx, Ebb, Etot);
    gather_kernel<<<(BN * 32 + 255) / 256, 256>>>();                       // 4 <- profiled
    info_dot_kernel<<<1184, 256>>>(X_B);                                   // 5
    finalize_kernel<<<1, 256>>>(vq_grad, b_conv, wr, out + (out_size - 1));// 6
    y_kernel<<<(BN + YROWS - 1) / YROWS, 256>>>(X_B, out);                 // 7
}